// round 5
// baseline (speedup 1.0000x reference)
#include <cuda_runtime.h>
#include <cuda_bf16.h>
#include <math.h>
#include <cstdint>

// Shapes: B=256, R=2048, M=65536, L=64, H=4, BH=1024
typedef unsigned long long ull;

// ---------------- device scratch ----------------
__device__ float g_rsT[2048 * 256];                 // reservoir transposed [k][b]
__device__ float g_WkT[2048 * 256];                 // Wk transposed [k][n]
__device__ float g_pk[32 * 256 * 256];              // split-K partials for keys
__device__ signed char g_key_h[1024 * 64];          // quantized keys hi  [bh][l]
__device__ signed char g_key_l[1024 * 64];          // quantized keys lo
__device__ float       g_sck[1024];                 // key row scales
__device__ signed char g_mem_h[65536 * 64];         // quantized memory hi [m][l]
__device__ signed char g_mem_l[65536 * 64];         // quantized memory lo
__device__ float       g_scm[65536];                // memory row scales
__device__ float g_sumsP[1024 * 512];               // per (row, m-tile) partial expsums
__device__ float g_invsum[1024];

// ---------------- packed fp32 helpers (k1a) ----------------
__device__ __forceinline__ ull packdup(float x) {
    ull r; asm("mov.b64 %0, {%1, %1};" : "=l"(r) : "f"(x)); return r;
}
__device__ __forceinline__ ull pack2(float x, float y) {
    ull r; asm("mov.b64 %0, {%1, %2};" : "=l"(r) : "f"(x), "f"(y)); return r;
}
__device__ __forceinline__ void fma2(ull &d, ull a, ull b) {
    asm("fma.rn.f32x2 %0, %1, %2, %0;" : "+l"(d) : "l"(a), "l"(b));
}
__device__ __forceinline__ float2 unpack2(ull v) {
    float2 f; asm("mov.b64 {%0, %1}, %2;" : "=f"(f.x), "=f"(f.y) : "l"(v)); return f;
}

// ---------------- IMMA helper: m16n8k32 s8*s8 -> s32 ----------------
__device__ __forceinline__ void mma_s8(int* d, uint32_t a0, uint32_t a1,
                                       uint32_t a2, uint32_t a3,
                                       uint32_t b0, uint32_t b1) {
    asm volatile(
        "mma.sync.aligned.m16n8k32.row.col.s32.s8.s8.s32 "
        "{%0,%1,%2,%3}, {%4,%5,%6,%7}, {%8,%9}, {%0,%1,%2,%3};"
        : "+r"(d[0]), "+r"(d[1]), "+r"(d[2]), "+r"(d[3])
        : "r"(a0), "r"(a1), "r"(a2), "r"(a3), "r"(b0), "r"(b1));
}

// ---------------- transposes for k1 ----------------
__device__ __forceinline__ void transpose_body(const float* __restrict__ in,
                                               float* __restrict__ out, int rows, int cols) {
    __shared__ float t[32][33];
    int c0 = blockIdx.x * 32, r0 = blockIdx.y * 32;
#pragma unroll
    for (int j = 0; j < 4; j++)
        t[threadIdx.y + 8 * j][threadIdx.x] =
            in[(size_t)(r0 + threadIdx.y + 8 * j) * cols + c0 + threadIdx.x];
    __syncthreads();
#pragma unroll
    for (int j = 0; j < 4; j++)
        out[(size_t)(c0 + threadIdx.y + 8 * j) * rows + r0 + threadIdx.x] =
            t[threadIdx.x][threadIdx.y + 8 * j];
}
__global__ void t_rs(const float* __restrict__ in) { transpose_body(in, g_rsT, 256, 2048); }
__global__ void t_wk(const float* __restrict__ in) { transpose_body(in, g_WkT, 256, 2048); }

// ---------------- memory -> int16-split int8 (one warp per row) ----------------
__global__ void conv_mem(const float* __restrict__ in) {
    int row = (blockIdx.x * blockDim.x + threadIdx.x) >> 5;
    int lid = threadIdx.x & 31;
    float2 v = ((const float2*)in)[(size_t)row * 32 + lid];
    float mx = fmaxf(fabsf(v.x), fabsf(v.y));
#pragma unroll
    for (int o = 16; o > 0; o >>= 1) mx = fmaxf(mx, __shfl_xor_sync(0xffffffffu, mx, o));
    float qs = mx > 0.f ? 32639.f / mx : 0.f;
    int i0 = __float2int_rn(v.x * qs), i1 = __float2int_rn(v.y * qs);
    int h0 = (i0 + 128) >> 8, l0 = i0 - (h0 << 8);
    int h1 = (i1 + 128) >> 8, l1 = i1 - (h1 << 8);
    char2 hp, lp;
    hp.x = (signed char)h0; hp.y = (signed char)h1;
    lp.x = (signed char)l0; lp.y = (signed char)l1;
    *(char2*)&g_mem_h[row * 64 + lid * 2] = hp;
    *(char2*)&g_mem_l[row * 64 + lid * 2] = lp;
    if (lid == 0) g_scm[row] = mx > 0.f ? mx * (1.f / 32639.f) : 0.f;
}

// ---------------- k1a: split-K GEMM for key projection (fp32 FFMA2) ----------------
__global__ __launch_bounds__(256, 2) void k1a_keys_gemm() {
    int n0 = blockIdx.x * 128, b0 = blockIdx.y * 128, kb = blockIdx.z * 64;
    int tid = threadIdx.x, tx = tid & 15, ty = tid >> 4;
    __shared__ float At[32][128];
    __shared__ float Bt[32][128];
    ull acc[8][4];
#pragma unroll
    for (int i = 0; i < 8; i++)
#pragma unroll
        for (int j = 0; j < 4; j++) acc[i][j] = 0ull;

    for (int kc = 0; kc < 64; kc += 32) {
#pragma unroll
        for (int it = 0; it < 4; it++) {
            int idx = tid + it * 256;
            int r = idx >> 5, c = (idx & 31) * 4;
            *(float4*)&At[r][c] = *(const float4*)&g_rsT[(size_t)(kb + kc + r) * 256 + b0 + c];
            *(float4*)&Bt[r][c] = *(const float4*)&g_WkT[(size_t)(kb + kc + r) * 256 + n0 + c];
        }
        __syncthreads();
#pragma unroll 8
        for (int k = 0; k < 32; k++) {
            float4 a0 = *(float4*)&At[k][ty * 4];
            float4 a1 = *(float4*)&At[k][64 + ty * 4];
            float4 b0v = *(float4*)&Bt[k][tx * 4];
            float4 b1v = *(float4*)&Bt[k][64 + tx * 4];
            ull bp0 = pack2(b0v.x, b0v.y), bp1 = pack2(b0v.z, b0v.w);
            ull bp2 = pack2(b1v.x, b1v.y), bp3 = pack2(b1v.z, b1v.w);
            float av[8] = {a0.x, a0.y, a0.z, a0.w, a1.x, a1.y, a1.z, a1.w};
#pragma unroll
            for (int i = 0; i < 8; i++) {
                ull ad = packdup(av[i]);
                fma2(acc[i][0], ad, bp0); fma2(acc[i][1], ad, bp1);
                fma2(acc[i][2], ad, bp2); fma2(acc[i][3], ad, bp3);
            }
        }
        __syncthreads();
    }
    int z = blockIdx.z;
#pragma unroll
    for (int i = 0; i < 8; i++) {
        int rl = (i < 4) ? (ty * 4 + i) : (64 + ty * 4 + (i - 4));
        float2 v0 = unpack2(acc[i][0]), v1 = unpack2(acc[i][1]);
        float2 v2 = unpack2(acc[i][2]), v3 = unpack2(acc[i][3]);
        size_t base = (size_t)z * 65536 + (size_t)(b0 + rl) * 256 + n0;
        *(float4*)&g_pk[base + tx * 4]      = make_float4(v0.x, v0.y, v1.x, v1.y);
        *(float4*)&g_pk[base + 64 + tx * 4] = make_float4(v2.x, v2.y, v3.x, v3.y);
    }
}

// ---------------- k1b: finalize -> quantized scaled keys [bh][64] ----------------
__global__ void k1b_finalize(const float* __restrict__ rs, const float* __restrict__ Wb,
                             const float* __restrict__ bk, const float* __restrict__ bb) {
    int bh = blockIdx.x;
    int b = bh >> 2, h = bh & 3;
    int l = threadIdx.x;              // 64 threads
    int n = h * 64 + l;

    float key = bk[n];
#pragma unroll
    for (int s = 0; s < 32; s++) key += g_pk[(size_t)s * 65536 + b * 256 + n];

    float bp = 0.f;
#pragma unroll 8
    for (int i = 0; i < 32; i++)
        bp += rs[b * 2048 + l + 64 * i] * Wb[h * 2048 + l + 64 * i];

    __shared__ float s1[64], s2[64];
    s1[l] = key * key; s2[l] = bp;
    __syncthreads();
    for (int o = 32; o > 0; o >>= 1) {
        if (l < o) { s1[l] += s1[l + o]; s2[l] += s2[l + o]; }
        __syncthreads();
    }
    float beta = s2[0] + bb[h];
    beta = beta > 0.f ? beta : 0.f;
    float sk = key * (beta * rsqrtf(s1[0]));

    // quantize the scaled row to split-int16
    __syncthreads();
    s1[l] = fabsf(sk);
    __syncthreads();
    for (int o = 32; o > 0; o >>= 1) {
        if (l < o) s1[l] = fmaxf(s1[l], s1[l + o]);
        __syncthreads();
    }
    float mx = s1[0];
    float qs = mx > 0.f ? 32639.f / mx : 0.f;
    int iv = __float2int_rn(sk * qs);
    int hq = (iv + 128) >> 8, lq = iv - (hq << 8);
    g_key_h[bh * 64 + l] = (signed char)hq;
    g_key_l[bh * 64 + l] = (signed char)lq;
    if (l == 0) g_sck[bh] = mx > 0.f ? mx * (1.f / 32639.f) : 0.f;
}

// ---------------- k2: IMMA GEMM (128bh x 128m x K64, split-int16) ----------------
// PASS 0: exp row-sum partials only.  PASS 1: write exp * invsum to out.
// 8 warps 2x4; warp tile 64x32; mma.m16n8k32.s8; acc_h = hh, acc_m = hl+lh.
static constexpr int ROW_S = 80;                        // smem row stride (64B data + pad)
static constexpr int ARR_S = 128 * ROW_S;               // 10240 per array
static constexpr int SA_H = 0;
static constexpr int SA_L = ARR_S;
static constexpr int SB_H = 2 * ARR_S;
static constexpr int SB_L = 3 * ARR_S;
static constexpr int SPS  = 4 * ARR_S;                  // ps[128][4]
static constexpr int SMEM_K2 = SPS + 128 * 4 * 4;       // 43008

template <int PASS>
__global__ __launch_bounds__(256) void k2_imma(float* __restrict__ out) {
    extern __shared__ char smem[];
    int tid = threadIdx.x, wid = tid >> 5, lid = tid & 31;
    int wr = wid >> 2, wc = wid & 3;          // warp grid 2x4
    int g = lid >> 2, c = lid & 3;            // groupID / thread-in-group
    int mt = blockIdx.x, bt = blockIdx.y;
    int m0 = mt * 128, bh0 = bt * 128;

    // ---- fill smem: 2048 uint4 chunks (Ah, Al, Bh, Bl), 8 per thread
#pragma unroll
    for (int i = 0; i < 8; i++) {
        int it = tid + i * 256;
        int arr = it >> 9;                     // 0..3
        int rem = it & 511;
        int r = rem >> 2, c16 = rem & 3;
        const signed char* src;
        if (arr == 0)      src = g_key_h + (size_t)(bh0 + r) * 64;
        else if (arr == 1) src = g_key_l + (size_t)(bh0 + r) * 64;
        else if (arr == 2) src = g_mem_h + (size_t)(m0 + r) * 64;
        else               src = g_mem_l + (size_t)(m0 + r) * 64;
        *(uint4*)(smem + arr * ARR_S + r * ROW_S + c16 * 16) = ((const uint4*)src)[c16];
    }
    __syncthreads();

    int acc_h[4][4][4], acc_m[4][4][4];
#pragma unroll
    for (int mi = 0; mi < 4; mi++)
#pragma unroll
        for (int ni = 0; ni < 4; ni++)
#pragma unroll
            for (int q = 0; q < 4; q++) { acc_h[mi][ni][q] = 0; acc_m[mi][ni][q] = 0; }

    int aoff = (wr * 64 + g) * ROW_S + c * 4;
    int boff = (wc * 32 + g) * ROW_S + c * 4;

#pragma unroll
    for (int ks = 0; ks < 2; ks++) {
        int ko = ks * 32;
        uint32_t ah[4][4], al[4][4];
#pragma unroll
        for (int mi = 0; mi < 4; mi++) {
            int o = aoff + mi * 16 * ROW_S + ko;
            ah[mi][0] = *(const uint32_t*)(smem + SA_H + o);
            ah[mi][1] = *(const uint32_t*)(smem + SA_H + o + 8 * ROW_S);
            ah[mi][2] = *(const uint32_t*)(smem + SA_H + o + 16);
            ah[mi][3] = *(const uint32_t*)(smem + SA_H + o + 8 * ROW_S + 16);
            al[mi][0] = *(const uint32_t*)(smem + SA_L + o);
            al[mi][1] = *(const uint32_t*)(smem + SA_L + o + 8 * ROW_S);
            al[mi][2] = *(const uint32_t*)(smem + SA_L + o + 16);
            al[mi][3] = *(const uint32_t*)(smem + SA_L + o + 8 * ROW_S + 16);
        }
        uint32_t bh_[4][2], bl_[4][2];
#pragma unroll
        for (int ni = 0; ni < 4; ni++) {
            int o = boff + ni * 8 * ROW_S + ko;
            bh_[ni][0] = *(const uint32_t*)(smem + SB_H + o);
            bh_[ni][1] = *(const uint32_t*)(smem + SB_H + o + 16);
            bl_[ni][0] = *(const uint32_t*)(smem + SB_L + o);
            bl_[ni][1] = *(const uint32_t*)(smem + SB_L + o + 16);
        }
#pragma unroll
        for (int mi = 0; mi < 4; mi++)
#pragma unroll
            for (int ni = 0; ni < 4; ni++) {
                mma_s8(acc_h[mi][ni], ah[mi][0], ah[mi][1], ah[mi][2], ah[mi][3],
                       bh_[ni][0], bh_[ni][1]);
                mma_s8(acc_m[mi][ni], ah[mi][0], ah[mi][1], ah[mi][2], ah[mi][3],
                       bl_[ni][0], bl_[ni][1]);
                mma_s8(acc_m[mi][ni], al[mi][0], al[mi][1], al[mi][2], al[mi][3],
                       bh_[ni][0], bh_[ni][1]);
            }
    }

    // epilogue: logit = sck[row]*scm[col]*(65536*hh + 256*md)
    if (PASS == 0) {
        __syncthreads();
        float* ps = (float*)(smem + SPS);     // ps[128][4]
#pragma unroll
        for (int mi = 0; mi < 4; mi++) {
            int r0 = wr * 64 + mi * 16 + g;
            float kA = g_sck[bh0 + r0], kB = g_sck[bh0 + r0 + 8];
            float s0 = 0.f, s1 = 0.f;
#pragma unroll
            for (int ni = 0; ni < 4; ni++) {
                int col = m0 + wc * 32 + ni * 8 + 2 * c;
                float mA = g_scm[col], mB = g_scm[col + 1];
                float v0 = fmaf(65536.f, (float)acc_h[mi][ni][0], 256.f * (float)acc_m[mi][ni][0]);
                float v1 = fmaf(65536.f, (float)acc_h[mi][ni][1], 256.f * (float)acc_m[mi][ni][1]);
                float v2 = fmaf(65536.f, (float)acc_h[mi][ni][2], 256.f * (float)acc_m[mi][ni][2]);
                float v3 = fmaf(65536.f, (float)acc_h[mi][ni][3], 256.f * (float)acc_m[mi][ni][3]);
                s0 += __expf(kA * mA * v0) + __expf(kA * mB * v1);
                s1 += __expf(kB * mA * v2) + __expf(kB * mB * v3);
            }
            s0 += __shfl_xor_sync(0xffffffffu, s0, 1);
            s0 += __shfl_xor_sync(0xffffffffu, s0, 2);
            s1 += __shfl_xor_sync(0xffffffffu, s1, 1);
            s1 += __shfl_xor_sync(0xffffffffu, s1, 2);
            if (c == 0) {
                ps[r0 * 4 + wc] = s0;
                ps[(r0 + 8) * 4 + wc] = s1;
            }
        }
        __syncthreads();
        if (tid < 128) {
            float s = (ps[tid * 4 + 0] + ps[tid * 4 + 1]) + (ps[tid * 4 + 2] + ps[tid * 4 + 3]);
            g_sumsP[(size_t)(bh0 + tid) * 512 + mt] = s;
        }
    } else {
#pragma unroll
        for (int mi = 0; mi < 4; mi++) {
            int r0 = wr * 64 + mi * 16 + g;
            float kA = g_sck[bh0 + r0], kB = g_sck[bh0 + r0 + 8];
            float iA = g_invsum[bh0 + r0], iB = g_invsum[bh0 + r0 + 8];
            size_t obA = (size_t)(bh0 + r0) * 65536 + m0 + wc * 32;
            size_t obB = (size_t)(bh0 + r0 + 8) * 65536 + m0 + wc * 32;
#pragma unroll
            for (int ni = 0; ni < 4; ni++) {
                int colr = wc * 32 + ni * 8 + 2 * c;
                float mA = g_scm[m0 + colr], mB = g_scm[m0 + colr + 1];
                float v0 = fmaf(65536.f, (float)acc_h[mi][ni][0], 256.f * (float)acc_m[mi][ni][0]);
                float v1 = fmaf(65536.f, (float)acc_h[mi][ni][1], 256.f * (float)acc_m[mi][ni][1]);
                float v2 = fmaf(65536.f, (float)acc_h[mi][ni][2], 256.f * (float)acc_m[mi][ni][2]);
                float v3 = fmaf(65536.f, (float)acc_h[mi][ni][3], 256.f * (float)acc_m[mi][ni][3]);
                float2 w0 = make_float2(__expf(kA * mA * v0) * iA, __expf(kA * mB * v1) * iA);
                float2 w1 = make_float2(__expf(kB * mA * v2) * iB, __expf(kB * mB * v3) * iB);
                *(float2*)&out[obA + ni * 8 + 2 * c] = w0;
                *(float2*)&out[obB + ni * 8 + 2 * c] = w1;
            }
        }
    }
}

// ---------------- k3: reduce partial sums -> 1/rowsum ----------------
__global__ void k3_reduce() {
    int bh = blockIdx.x, t = threadIdx.x;   // 128 threads
    float s = 0.f;
#pragma unroll
    for (int j = 0; j < 4; j++) s += g_sumsP[(size_t)bh * 512 + t + 128 * j];
    __shared__ float red[128];
    red[t] = s;
    __syncthreads();
    for (int o = 64; o > 0; o >>= 1) {
        if (t < o) red[t] += red[t + o];
        __syncthreads();
    }
    if (t == 0) g_invsum[bh] = 1.0f / red[0];
}

// ---------------- launch ----------------
extern "C" void kernel_launch(void* const* d_in, const int* in_sizes, int n_in,
                              void* d_out, int out_size) {
    const float* rs  = (const float*)d_in[0];   // [256, 2048]
    const float* mem = (const float*)d_in[1];   // [1, 65536, 64]
    const float* Wk  = (const float*)d_in[2];   // [256, 2048]
    const float* bk  = (const float*)d_in[3];   // [256]
    const float* Wb  = (const float*)d_in[4];   // [4, 2048]
    const float* bb  = (const float*)d_in[5];   // [4]
    float* out = (float*)d_out;                 // [256, 4, 65536]
    (void)in_sizes; (void)n_in; (void)out_size;

    cudaFuncSetAttribute(k2_imma<0>, cudaFuncAttributeMaxDynamicSharedMemorySize, SMEM_K2);
    cudaFuncSetAttribute(k2_imma<1>, cudaFuncAttributeMaxDynamicSharedMemorySize, SMEM_K2);

    dim3 tb(32, 8);
    conv_mem<<<8192, 256>>>(mem);
    t_rs<<<dim3(64, 8), tb>>>(rs);
    t_wk<<<dim3(64, 8), tb>>>(Wk);

    k1a_keys_gemm<<<dim3(2, 2, 32), 256>>>();
    k1b_finalize<<<1024, 64>>>(rs, Wb, bk, bb);

    k2_imma<0><<<dim3(512, 8), 256, SMEM_K2>>>(nullptr);
    k3_reduce<<<1024, 128>>>();
    k2_imma<1><<<dim3(512, 8), 256, SMEM_K2>>>(out);
}

// round 6
// speedup vs baseline: 2.4735x; 2.4735x over previous
#include <cuda_runtime.h>
#include <cuda_bf16.h>
#include <math.h>
#include <cstdint>

// Shapes: B=256, R=2048, M=65536, L=64, H=4, BH=1024
typedef unsigned long long ull;

// ---------------- device scratch ----------------
__device__ float g_rsT[2048 * 256];                 // reservoir transposed [k][b]
__device__ float g_WkT[2048 * 256];                 // Wk transposed [k][n]
__device__ float g_pk[64 * 256 * 256];              // split-K partials for keys
__device__ __nv_bfloat16 g_key_hi[1024 * 64];       // scaled keys, bf16 hi  [bh][l]
__device__ __nv_bfloat16 g_key_lo[1024 * 64];       // scaled keys, bf16 lo
__device__ __nv_bfloat16 g_mem_hi[65536 * 64];      // memory, bf16 hi [m][l]
__device__ __nv_bfloat16 g_mem_lo[65536 * 64];      // memory, bf16 lo
__device__ float g_sumsP[1024 * 512];               // per (row, m-tile) partial expsums
__device__ float g_invsum[1024];

// ---------------- packed fp32 helpers (k1a) ----------------
__device__ __forceinline__ ull packdup(float x) {
    ull r; asm("mov.b64 %0, {%1, %1};" : "=l"(r) : "f"(x)); return r;
}
__device__ __forceinline__ ull pack2(float x, float y) {
    ull r; asm("mov.b64 %0, {%1, %2};" : "=l"(r) : "f"(x), "f"(y)); return r;
}
__device__ __forceinline__ void fma2(ull &d, ull a, ull b) {
    asm("fma.rn.f32x2 %0, %1, %2, %0;" : "+l"(d) : "l"(a), "l"(b));
}
__device__ __forceinline__ float2 unpack2(ull v) {
    float2 f; asm("mov.b64 {%0, %1}, %2;" : "=f"(f.x), "=f"(f.y) : "l"(v)); return f;
}

// ---------------- HMMA / ldmatrix helpers ----------------
__device__ __forceinline__ void mma_bf16(float* d, uint32_t a0, uint32_t a1,
                                         uint32_t a2, uint32_t a3,
                                         uint32_t b0, uint32_t b1) {
    asm volatile(
        "mma.sync.aligned.m16n8k16.row.col.f32.bf16.bf16.f32 "
        "{%0,%1,%2,%3}, {%4,%5,%6,%7}, {%8,%9}, {%0,%1,%2,%3};"
        : "+f"(d[0]), "+f"(d[1]), "+f"(d[2]), "+f"(d[3])
        : "r"(a0), "r"(a1), "r"(a2), "r"(a3), "r"(b0), "r"(b1));
}
__device__ __forceinline__ void ldsm_x4(uint32_t& r0, uint32_t& r1, uint32_t& r2,
                                        uint32_t& r3, uint32_t addr) {
    asm volatile("ldmatrix.sync.aligned.m8n8.x4.shared.b16 {%0,%1,%2,%3}, [%4];"
                 : "=r"(r0), "=r"(r1), "=r"(r2), "=r"(r3) : "r"(addr));
}
__device__ __forceinline__ uint32_t smem_u32(const void* p) {
    uint32_t a;
    asm("{ .reg .u64 t; cvta.to.shared.u64 t, %1; cvt.u32.u64 %0, t; }" : "=r"(a) : "l"(p));
    return a;
}

// ---------------- transposes for k1 (merged) ----------------
__device__ __forceinline__ void transpose_body(const float* __restrict__ in,
                                               float* __restrict__ out, int rows, int cols) {
    __shared__ float t[32][33];
    int c0 = blockIdx.x * 32, r0 = blockIdx.y * 32;
#pragma unroll
    for (int j = 0; j < 4; j++)
        t[threadIdx.y + 8 * j][threadIdx.x] =
            in[(size_t)(r0 + threadIdx.y + 8 * j) * cols + c0 + threadIdx.x];
    __syncthreads();
#pragma unroll
    for (int j = 0; j < 4; j++)
        out[(size_t)(c0 + threadIdx.y + 8 * j) * rows + r0 + threadIdx.x] =
            t[threadIdx.x][threadIdx.y + 8 * j];
}
__global__ void t_both(const float* __restrict__ rs, const float* __restrict__ wk) {
    if (blockIdx.z == 0) transpose_body(rs, g_rsT, 256, 2048);
    else                 transpose_body(wk, g_WkT, 256, 2048);
}

// ---------------- memory -> bf16 hi/lo ----------------
__global__ void conv_mem(const float* __restrict__ in) {
    size_t i = (size_t)blockIdx.x * 256 + threadIdx.x;     // group of 8 floats
    const float4* p = (const float4*)in + i * 2;
    float4 a = p[0], b = p[1];
    float v[8] = {a.x, a.y, a.z, a.w, b.x, b.y, b.z, b.w};
    __align__(16) __nv_bfloat16 hh[8], ll[8];
#pragma unroll
    for (int j = 0; j < 8; j++) {
        hh[j] = __float2bfloat16_rn(v[j]);
        ll[j] = __float2bfloat16_rn(v[j] - __bfloat162float(hh[j]));
    }
    *(uint4*)&g_mem_hi[i * 8] = *(uint4*)hh;
    *(uint4*)&g_mem_lo[i * 8] = *(uint4*)ll;
}

// ---------------- k1a: split-K GEMM for key projection (K chunk 32) ----------------
// grid (2 n-tiles, 2 b-tiles, 64 k-splits), 256 threads, 128x128 tile
__global__ __launch_bounds__(256, 2) void k1a_keys_gemm() {
    int n0 = blockIdx.x * 128, b0 = blockIdx.y * 128, kb = blockIdx.z * 32;
    int tid = threadIdx.x, tx = tid & 15, ty = tid >> 4;
    __shared__ float At[32][128];
    __shared__ float Bt[32][128];
    ull acc[8][4];
#pragma unroll
    for (int i = 0; i < 8; i++)
#pragma unroll
        for (int j = 0; j < 4; j++) acc[i][j] = 0ull;

#pragma unroll
    for (int it = 0; it < 4; it++) {
        int idx = tid + it * 256;
        int r = idx >> 5, c = (idx & 31) * 4;
        *(float4*)&At[r][c] = *(const float4*)&g_rsT[(size_t)(kb + r) * 256 + b0 + c];
        *(float4*)&Bt[r][c] = *(const float4*)&g_WkT[(size_t)(kb + r) * 256 + n0 + c];
    }
    __syncthreads();
#pragma unroll 8
    for (int k = 0; k < 32; k++) {
        float4 a0 = *(float4*)&At[k][ty * 4];
        float4 a1 = *(float4*)&At[k][64 + ty * 4];
        float4 b0v = *(float4*)&Bt[k][tx * 4];
        float4 b1v = *(float4*)&Bt[k][64 + tx * 4];
        ull bp0 = pack2(b0v.x, b0v.y), bp1 = pack2(b0v.z, b0v.w);
        ull bp2 = pack2(b1v.x, b1v.y), bp3 = pack2(b1v.z, b1v.w);
        float av[8] = {a0.x, a0.y, a0.z, a0.w, a1.x, a1.y, a1.z, a1.w};
#pragma unroll
        for (int i = 0; i < 8; i++) {
            ull ad = packdup(av[i]);
            fma2(acc[i][0], ad, bp0); fma2(acc[i][1], ad, bp1);
            fma2(acc[i][2], ad, bp2); fma2(acc[i][3], ad, bp3);
        }
    }
    int z = blockIdx.z;
#pragma unroll
    for (int i = 0; i < 8; i++) {
        int rl = (i < 4) ? (ty * 4 + i) : (64 + ty * 4 + (i - 4));
        float2 v0 = unpack2(acc[i][0]), v1 = unpack2(acc[i][1]);
        float2 v2 = unpack2(acc[i][2]), v3 = unpack2(acc[i][3]);
        size_t base = (size_t)z * 65536 + (size_t)(b0 + rl) * 256 + n0;
        *(float4*)&g_pk[base + tx * 4]      = make_float4(v0.x, v0.y, v1.x, v1.y);
        *(float4*)&g_pk[base + 64 + tx * 4] = make_float4(v2.x, v2.y, v3.x, v3.y);
    }
}

// ---------------- k1b: finalize -> scaled bf16 hi/lo keys [bh][64] ----------------
__global__ void k1b_finalize(const float* __restrict__ rs, const float* __restrict__ Wb,
                             const float* __restrict__ bk, const float* __restrict__ bb) {
    int bh = blockIdx.x;
    int b = bh >> 2, h = bh & 3;
    int l = threadIdx.x;              // 64 threads
    int n = h * 64 + l;

    float key = bk[n];
#pragma unroll
    for (int s = 0; s < 64; s++) key += g_pk[(size_t)s * 65536 + b * 256 + n];

    float bp = 0.f;
#pragma unroll 8
    for (int i = 0; i < 32; i++)
        bp += rs[b * 2048 + l + 64 * i] * Wb[h * 2048 + l + 64 * i];

    __shared__ float s1[64], s2[64];
    s1[l] = key * key; s2[l] = bp;
    __syncthreads();
    for (int o = 32; o > 0; o >>= 1) {
        if (l < o) { s1[l] += s1[l + o]; s2[l] += s2[l + o]; }
        __syncthreads();
    }
    float beta = s2[0] + bb[h];
    beta = beta > 0.f ? beta : 0.f;
    float sk = key * (beta * rsqrtf(s1[0]));
    __nv_bfloat16 hi = __float2bfloat16_rn(sk);
    __nv_bfloat16 lo = __float2bfloat16_rn(sk - __bfloat162float(hi));
    g_key_hi[bh * 64 + l] = hi;
    g_key_lo[bh * 64 + l] = lo;
}

// ---------------- k2: HMMA GEMM (128bh x 128m x K64, 3-term bf16 split) ----------------
// PASS 0: exp row-sum partials only.  PASS 1: write exp(d) * invsum to out.
// 8 warps 2x4, warp tile 64x32, ldmatrix fragment loads.
static constexpr int ROW_B = 144;                    // smem row stride in bytes
static constexpr int SM_A_HI = 0;
static constexpr int SM_A_LO = SM_A_HI + 128 * ROW_B;   // 18432
static constexpr int SM_B_HI = SM_A_LO + 128 * ROW_B;   // 36864
static constexpr int SM_B_LO = SM_B_HI + 128 * ROW_B;   // 55296
static constexpr int SMEM_K2 = SM_B_LO + 128 * ROW_B;   // 73728

template <int PASS>
__global__ __launch_bounds__(256, 2) void k2_mma(float* __restrict__ out) {
    extern __shared__ char smem[];
    int tid = threadIdx.x, wid = tid >> 5, lid = tid & 31;
    int wr = wid >> 2, wc = wid & 3;          // warp grid 2x4
    int g = lid >> 2, c = lid & 3;            // groupID / thread-in-group
    int mt = blockIdx.x, bt = blockIdx.y;
    int m0 = mt * 128, bh0 = bt * 128;

    // ---- fill smem: 1024 chunk-ids x 4 arrays; 64 bf16/row -> 8x16B, stride 144
#pragma unroll
    for (int i = 0; i < 4; i++) {
        int it = tid + i * 256;               // 1024 chunks of 16B
        int r = it >> 3, c16 = it & 7;
        int dof = r * ROW_B + c16 * 16;
        *(uint4*)(smem + SM_A_HI + dof) = ((const uint4*)(g_key_hi + (size_t)(bh0 + r) * 64))[c16];
        *(uint4*)(smem + SM_A_LO + dof) = ((const uint4*)(g_key_lo + (size_t)(bh0 + r) * 64))[c16];
        *(uint4*)(smem + SM_B_HI + dof) = ((const uint4*)(g_mem_hi + (size_t)(m0 + r) * 64))[c16];
        *(uint4*)(smem + SM_B_LO + dof) = ((const uint4*)(g_mem_lo + (size_t)(m0 + r) * 64))[c16];
    }
    __syncthreads();

    float acc[4][4][4];
#pragma unroll
    for (int mi = 0; mi < 4; mi++)
#pragma unroll
        for (int ni = 0; ni < 4; ni++)
#pragma unroll
            for (int q = 0; q < 4; q++) acc[mi][ni][q] = 0.f;

    // ldmatrix lane addresses
    uint32_t sb = smem_u32(smem);
    int rw = lid & 7;
    uint32_t aAddr = sb + (uint32_t)((wr * 64 + rw + ((lid >> 3) & 1) * 8) * ROW_B
                                     + ((lid >> 4) & 1) * 16);
    uint32_t bAddr = sb + (uint32_t)((wc * 32 + rw + ((lid >> 4) & 1) * 8) * ROW_B
                                     + ((lid >> 3) & 1) * 16);

#pragma unroll
    for (int kk = 0; kk < 4; kk++) {
        uint32_t ah[4][4], al[4][4];
#pragma unroll
        for (int mi = 0; mi < 4; mi++) {
            uint32_t ao = aAddr + mi * 16 * ROW_B + kk * 32;
            ldsm_x4(ah[mi][0], ah[mi][1], ah[mi][2], ah[mi][3], ao + SM_A_HI);
            ldsm_x4(al[mi][0], al[mi][1], al[mi][2], al[mi][3], ao + SM_A_LO);
        }
#pragma unroll
        for (int p = 0; p < 2; p++) {
            uint32_t bh_[4], bl_[4];
            uint32_t bo = bAddr + p * 16 * ROW_B + kk * 32;
            ldsm_x4(bh_[0], bh_[1], bh_[2], bh_[3], bo + SM_B_HI);
            ldsm_x4(bl_[0], bl_[1], bl_[2], bl_[3], bo + SM_B_LO);
#pragma unroll
            for (int mi = 0; mi < 4; mi++)
#pragma unroll
                for (int q = 0; q < 2; q++) {
                    int ni = p * 2 + q;
                    mma_bf16(acc[mi][ni], ah[mi][0], ah[mi][1], ah[mi][2], ah[mi][3],
                             bh_[q * 2], bh_[q * 2 + 1]);
                    mma_bf16(acc[mi][ni], ah[mi][0], ah[mi][1], ah[mi][2], ah[mi][3],
                             bl_[q * 2], bl_[q * 2 + 1]);
                    mma_bf16(acc[mi][ni], al[mi][0], al[mi][1], al[mi][2], al[mi][3],
                             bh_[q * 2], bh_[q * 2 + 1]);
                }
        }
    }

    if (PASS == 0) {
        // exp row-sum partials; acc regs: d0 (g,2c), d1 (g,2c+1), d2 (g+8,2c), d3 (g+8,2c+1)
        __syncthreads();
        float* ps = (float*)smem;             // ps[row 128][wc 4]
#pragma unroll
        for (int mi = 0; mi < 4; mi++) {
            float s0 = 0.f, s1 = 0.f;
#pragma unroll
            for (int ni = 0; ni < 4; ni++) {
                s0 += __expf(acc[mi][ni][0]) + __expf(acc[mi][ni][1]);
                s1 += __expf(acc[mi][ni][2]) + __expf(acc[mi][ni][3]);
            }
            s0 += __shfl_xor_sync(0xffffffffu, s0, 1);
            s0 += __shfl_xor_sync(0xffffffffu, s0, 2);
            s1 += __shfl_xor_sync(0xffffffffu, s1, 1);
            s1 += __shfl_xor_sync(0xffffffffu, s1, 2);
            if (c == 0) {
                int r0 = wr * 64 + mi * 16 + g;
                ps[r0 * 4 + wc] = s0;
                ps[(r0 + 8) * 4 + wc] = s1;
            }
        }
        __syncthreads();
        if (tid < 128) {
            float s = (ps[tid * 4 + 0] + ps[tid * 4 + 1]) + (ps[tid * 4 + 2] + ps[tid * 4 + 3]);
            g_sumsP[(size_t)(bh0 + tid) * 512 + mt] = s;
        }
    } else {
#pragma unroll
        for (int mi = 0; mi < 4; mi++) {
            int r0 = bh0 + wr * 64 + mi * 16 + g;
            float i0 = g_invsum[r0], i1 = g_invsum[r0 + 8];
            size_t ob0 = (size_t)r0 * 65536 + m0 + wc * 32;
            size_t ob1 = (size_t)(r0 + 8) * 65536 + m0 + wc * 32;
#pragma unroll
            for (int ni = 0; ni < 4; ni++) {
                int col = ni * 8 + 2 * c;
                float2 v0 = make_float2(__expf(acc[mi][ni][0]) * i0, __expf(acc[mi][ni][1]) * i0);
                float2 v1 = make_float2(__expf(acc[mi][ni][2]) * i1, __expf(acc[mi][ni][3]) * i1);
                *(float2*)&out[ob0 + col] = v0;
                *(float2*)&out[ob1 + col] = v1;
            }
        }
    }
}

// ---------------- k3: reduce partial sums -> 1/rowsum ----------------
__global__ void k3_reduce() {
    int bh = blockIdx.x, t = threadIdx.x;   // 128 threads
    float s = 0.f;
#pragma unroll
    for (int j = 0; j < 4; j++) s += g_sumsP[(size_t)bh * 512 + t + 128 * j];
    __shared__ float red[128];
    red[t] = s;
    __syncthreads();
    for (int o = 64; o > 0; o >>= 1) {
        if (t < o) red[t] += red[t + o];
        __syncthreads();
    }
    if (t == 0) g_invsum[bh] = 1.0f / red[0];
}

// ---------------- launch ----------------
extern "C" void kernel_launch(void* const* d_in, const int* in_sizes, int n_in,
                              void* d_out, int out_size) {
    const float* rs  = (const float*)d_in[0];   // [256, 2048]
    const float* mem = (const float*)d_in[1];   // [1, 65536, 64]
    const float* Wk  = (const float*)d_in[2];   // [256, 2048]
    const float* bk  = (const float*)d_in[3];   // [256]
    const float* Wb  = (const float*)d_in[4];   // [4, 2048]
    const float* bb  = (const float*)d_in[5];   // [4]
    float* out = (float*)d_out;                 // [256, 4, 65536]
    (void)in_sizes; (void)n_in; (void)out_size;

    cudaFuncSetAttribute(k2_mma<0>, cudaFuncAttributeMaxDynamicSharedMemorySize, SMEM_K2);
    cudaFuncSetAttribute(k2_mma<1>, cudaFuncAttributeMaxDynamicSharedMemorySize, SMEM_K2);

    dim3 tb(32, 8);
    conv_mem<<<2048, 256>>>(mem);
    t_both<<<dim3(64, 8, 2), tb>>>(rs, Wk);

    k1a_keys_gemm<<<dim3(2, 2, 64), 256>>>();
    k1b_finalize<<<1024, 64>>>(rs, Wb, bk, bb);

    k2_mma<0><<<dim3(512, 8), 256, SMEM_K2>>>(nullptr);
    k3_reduce<<<1024, 128>>>();
    k2_mma<1><<<dim3(512, 8), 256, SMEM_K2>>>(out);
}